// round 8
// baseline (speedup 1.0000x reference)
#include <cuda_runtime.h>
#include <math.h>
#include <stdint.h>

#define NB   32
#define CD   512
#define TD   2048
#define NT   (NB * TD)        // 65536
#define KCODE 512
#define QL   6
#define NCT  (NB * CD * TD)   // 33554432

#define IDX_OFF   ((size_t)NCT)
#define LOSS_OFF  (IDX_OFF + (size_t)NT * QL)   // 33947648
#define OUT_TOTAL (LOSS_OFF + 2)                 // 33947650

#define FULLM 0xffffffffu

// ---------------- device scratch (static globals; no runtime alloc) -------
__device__ float g_res[(size_t)NT * CD];   // residual state, row-major [(n,t), c]
__device__ float g_cc[QL * KCODE];         // ||c||^2, serial ascending schedule
__device__ int   g_code[QL * NT];
__device__ float g_hist[QL * KCODE];
__device__ float g_losspart[QL * 1024];

// ---------------- prep: zero hist + code norms ----------------------------
// XLA:CPU non-vectorized reduce: strictly serial ascending, separate mul/add.
__global__ void prep_kernel(const float* __restrict__ cb)
{
    int gid = blockIdx.x * 256 + threadIdx.x;
    if (gid < QL * KCODE) {
        g_hist[gid] = 0.0f;
        const float* row = cb + (size_t)gid * CD;
        float a = 0.0f;
        #pragma unroll 8
        for (int k = 0; k < CD; k++) {
            float v = row[k];
            a = __fadd_rn(a, __fmul_rn(v, v));
        }
        g_cc[gid] = a;
    }
}

// ---------------- transpose x [N,C,T] -> residual [(n,t), c] --------------
__global__ void transpose_in_kernel(const float* __restrict__ x)
{
    __shared__ float s[32][33];
    int n = blockIdx.z, c0 = blockIdx.y * 32, t0 = blockIdx.x * 32;
    int tx = threadIdx.x, ty = threadIdx.y;
    #pragma unroll
    for (int i = 0; i < 4; i++) {
        int cc = ty + 8 * i;
        s[cc][tx] = x[(size_t)n * CD * TD + (size_t)(c0 + cc) * TD + t0 + tx];
    }
    __syncthreads();
    #pragma unroll
    for (int i = 0; i < 4; i++) {
        int tt = ty + 8 * i;
        g_res[(size_t)(n * TD + t0 + tt) * CD + c0 + tx] = s[tx][tt];
    }
}

// ---------------- fused VQ layer: scores + argmin + update ----------------
#define SA_STRIDE 66
#define SA_WORDS  (512 * SA_STRIDE)
#define SB_WORDS  (8 * 512)
#define SMEM_FLOATS (SA_WORDS + 2 * SB_WORDS + 512 + 16)
#define SMEM_BYTES (SMEM_FLOATS * 4)

__global__ __launch_bounds__(256, 1) void vq_layer_kernel(const float* __restrict__ cb_all, int q)
{
    extern __shared__ float sm[];
    float* sA  = sm;
    float* sB  = sm + SA_WORDS;
    float* sCc = sm + SA_WORDS + 2 * SB_WORDS;
    float* sSt = sCc + 512;

    const float* cbq = cb_all + (size_t)q * KCODE * CD;
    const int t = threadIdx.x;
    const int bid = blockIdx.x;
    const int r0 = bid * 64;

    for (int i = t; i < 512; i += 256) sCc[i] = g_cc[q * 512 + i];

    // stage A (64 rows x 512) into [k][row] layout
    const float* resblk = g_res + (size_t)r0 * CD;
    #pragma unroll 4
    for (int j = 0; j < 128; j++) {
        int e = t + 256 * j;
        int row = e >> 9;
        int k = e & 511;
        sA[k * SA_STRIDE + row] = resblk[e];
    }

    // stage first B chunk
    float4 p0, p1, p2, p3;
    {
        const float* b0 = cbq + (size_t)t * CD;
        const float* b1 = cbq + (size_t)(t + 256) * CD;
        p0 = *(const float4*)b0;       p1 = *(const float4*)(b0 + 4);
        p2 = *(const float4*)b1;       p3 = *(const float4*)(b1 + 4);
    }
    {
        float* d = sB;
        d[0*512 + t] = p0.x; d[1*512 + t] = p0.y; d[2*512 + t] = p0.z; d[3*512 + t] = p0.w;
        d[4*512 + t] = p1.x; d[5*512 + t] = p1.y; d[6*512 + t] = p1.z; d[7*512 + t] = p1.w;
        d[0*512 + t+256] = p2.x; d[1*512 + t+256] = p2.y; d[2*512 + t+256] = p2.z; d[3*512 + t+256] = p2.w;
        d[4*512 + t+256] = p3.x; d[5*512 + t+256] = p3.y; d[6*512 + t+256] = p3.z; d[7*512 + t+256] = p3.w;
    }
    __syncthreads();

    unsigned long long acc[8][8];
    #pragma unroll
    for (int rr = 0; rr < 8; rr++)
        #pragma unroll
        for (int i = 0; i < 8; i++) acc[rr][i] = 0ull;

    const int w = t >> 5, l = t & 31;
    const int arow = 8 * w;

    // k strictly ascending, single fp32 accumulator per output, FMA
    // (bit-matches Eigen gebp serial-k fused-madd chain)
    #pragma unroll 1
    for (int kc = 0; kc < 512; kc += 8) {
        const int buf = (kc >> 3) & 1;
        const float* sBc = sB + buf * SB_WORDS;
        const bool more = (kc + 8) < 512;
        if (more) {
            const float* b0 = cbq + (size_t)t * CD + kc + 8;
            const float* b1 = cbq + (size_t)(t + 256) * CD + kc + 8;
            p0 = *(const float4*)b0;  p1 = *(const float4*)(b0 + 4);
            p2 = *(const float4*)b1;  p3 = *(const float4*)(b1 + 4);
        }
        #pragma unroll
        for (int kk = 0; kk < 8; kk++) {
            unsigned long long b2[8];
            #pragma unroll
            for (int i = 0; i < 8; i++)
                b2[i] = *(const unsigned long long*)(sBc + kk * 512 + 2 * l + 64 * i);
            #pragma unroll
            for (int rr = 0; rr < 8; rr++) {
                float av = sA[(kc + kk) * SA_STRIDE + arow + rr];
                unsigned au = __float_as_uint(av);
                unsigned long long a2;
                asm("mov.b64 %0, {%1, %1};" : "=l"(a2) : "r"(au));
                #pragma unroll
                for (int i = 0; i < 8; i++)
                    asm("fma.rn.f32x2 %0, %1, %2, %0;"
                        : "+l"(acc[rr][i]) : "l"(a2), "l"(b2[i]));
            }
        }
        if (more) {
            float* d = sB + (buf ^ 1) * SB_WORDS;
            d[0*512 + t] = p0.x; d[1*512 + t] = p0.y; d[2*512 + t] = p0.z; d[3*512 + t] = p0.w;
            d[4*512 + t] = p1.x; d[5*512 + t] = p1.y; d[6*512 + t] = p1.z; d[7*512 + t] = p1.w;
            d[0*512 + t+256] = p2.x; d[1*512 + t+256] = p2.y; d[2*512 + t+256] = p2.z; d[3*512 + t+256] = p2.w;
            d[4*512 + t+256] = p3.x; d[5*512 + t+256] = p3.y; d[6*512 + t+256] = p3.z; d[7*512 + t+256] = p3.w;
        }
        __syncthreads();
    }

    // ---- xx per row: strictly serial ascending scalar (XLA:CPU schedule) ----
    // lanes 0..7 each own one row of this warp's 8 rows; single accumulator,
    // separate mul/add, k = 0..511 ascending. Bank-conflict-free (consecutive rows).
    float xxser = 0.0f;
    if (l < 8) {
        const int row = arow + l;
        float a = 0.0f;
        #pragma unroll 8
        for (int k = 0; k < 512; k++) {
            float v = sA[k * SA_STRIDE + row];
            a = __fadd_rn(a, __fmul_rn(v, v));
        }
        xxser = a;
    }

    // epilogue: dist = (xx - 2*dot) + cc, argmin (min-index ties), ST update
    float warploss = 0.0f;
    #pragma unroll 1
    for (int rr = 0; rr < 8; rr++) {
        const int row = arow + rr;
        const float xx = __shfl_sync(FULLM, xxser, rr);

        float best = 3.4e38f; int bidx = 0;
        #pragma unroll
        for (int i = 0; i < 8; i++) {
            unsigned long long v = acc[rr][i];
            float d0 = __uint_as_float((unsigned)(v & 0xffffffffull));
            float d1 = __uint_as_float((unsigned)(v >> 32));
            int c0 = 2 * l + 64 * i;
            float dist0 = __fadd_rn(__fsub_rn(xx, __fmul_rn(2.0f, d0)), sCc[c0]);
            float dist1 = __fadd_rn(__fsub_rn(xx, __fmul_rn(2.0f, d1)), sCc[c0 + 1]);
            if (dist0 < best) { best = dist0; bidx = c0; }
            if (dist1 < best) { best = dist1; bidx = c0 + 1; }
        }
        #pragma unroll
        for (int o = 16; o; o >>= 1) {
            float ob = __shfl_xor_sync(FULLM, best, o);
            int   oi = __shfl_xor_sync(FULLM, bidx, o);
            if (ob < best || (ob == best && oi < bidx)) { best = ob; bidx = oi; }
        }

        // straight-through residual update replicated op-for-op + commit loss
        const float* crow = cbq + (size_t)bidx * CD;
        float* rrow = g_res + (size_t)(r0 + row) * CD;
        #pragma unroll
        for (int j = 0; j < 16; j++) {
            int k = l + 32 * j;
            float r = sA[k * SA_STRIDE + row];
            float c = crow[k];
            float xst  = __fadd_rn(r, __fsub_rn(c, r));   // xf + (x_d - xf)
            rrow[k]    = __fsub_rn(r, xst);               // residual - quantized
            float diff = __fsub_rn(r, c);                 // xf - x_d
            warploss += diff * diff;                      // scalar; loose tolerance
        }
        if (l == 0) {
            g_code[q * NT + r0 + row] = bidx;
            atomicAdd(&g_hist[q * 512 + bidx], 1.0f);
        }
    }
    #pragma unroll
    for (int o = 16; o; o >>= 1) warploss += __shfl_xor_sync(FULLM, warploss, o);
    if (l == 0) sSt[w] = warploss;
    __syncthreads();
    if (t == 0) {
        float s = 0.0f;
        #pragma unroll
        for (int i = 0; i < 8; i++) s += sSt[i];
        g_losspart[q * 1024 + bid] = s;
    }
}

// ---------------- output: quantized = x - residual_final (transposed) -----
__global__ void write_quant_kernel(const float* __restrict__ x, float* __restrict__ out)
{
    __shared__ float s[32][33];
    int n = blockIdx.z, c0 = blockIdx.y * 32, t0 = blockIdx.x * 32;
    int tx = threadIdx.x, ty = threadIdx.y;
    #pragma unroll
    for (int i = 0; i < 4; i++) {
        int tt = ty + 8 * i;
        s[tt][tx] = g_res[(size_t)(n * TD + t0 + tt) * CD + c0 + tx];
    }
    __syncthreads();
    #pragma unroll
    for (int i = 0; i < 4; i++) {
        int cc = ty + 8 * i;
        size_t o = (size_t)n * CD * TD + (size_t)(c0 + cc) * TD + t0 + tx;
        out[o] = __fsub_rn(x[o], s[tx][cc]);
    }
}

__global__ void write_idx_kernel(float* __restrict__ out, int out_size)
{
    int nt = blockIdx.x * 256 + threadIdx.x;
    if (nt < NT && (size_t)out_size >= OUT_TOTAL) {
        #pragma unroll
        for (int q = 0; q < QL; q++)
            out[IDX_OFF + (size_t)nt * QL + q] = (float)g_code[q * NT + nt];
    }
}

__global__ void finalize_kernel(float* __restrict__ out, int out_size)
{
    __shared__ float red[512];
    const int t = threadIdx.x;
    float tot_loss = 0.0f, tot_perp = 0.0f;
    for (int q = 0; q < QL; q++) {
        red[t] = g_losspart[q * 1024 + t] + g_losspart[q * 1024 + 512 + t];
        __syncthreads();
        for (int st = 256; st > 0; st >>= 1) {
            if (t < st) red[t] += red[t + st];
            __syncthreads();
        }
        tot_loss += red[0];
        __syncthreads();

        float p = g_hist[q * 512 + t] * (1.0f / 65536.0f);
        red[t] = p * logf(p + 1e-7f);
        __syncthreads();
        for (int st = 256; st > 0; st >>= 1) {
            if (t < st) red[t] += red[t + st];
            __syncthreads();
        }
        tot_perp += expf(-red[0]);
        __syncthreads();
    }
    if (t == 0 && (size_t)out_size >= OUT_TOTAL) {
        out[LOSS_OFF]     = tot_loss * (1.0f / ((float)NT * (float)CD)) / (float)QL;
        out[LOSS_OFF + 1] = tot_perp / (float)QL;
    }
}

// ---------------- launch --------------------------------------------------
extern "C" void kernel_launch(void* const* d_in, const int* in_sizes, int n_in,
                              void* d_out, int out_size)
{
    const float* x  = (const float*)d_in[0];
    const float* cb = (const float*)d_in[1];
    if (n_in >= 2 && in_sizes[0] < in_sizes[1]) {
        const float* tmp = x; x = cb; cb = tmp;
    }
    float* out = (float*)d_out;

    cudaFuncSetAttribute(vq_layer_kernel,
                         cudaFuncAttributeMaxDynamicSharedMemorySize, SMEM_BYTES);

    prep_kernel<<<384, 256>>>(cb);
    transpose_in_kernel<<<dim3(TD / 32, CD / 32, NB), dim3(32, 8)>>>(x);
    for (int q = 0; q < QL; q++)
        vq_layer_kernel<<<NT / 64, 256, SMEM_BYTES>>>(cb, q);
    write_quant_kernel<<<dim3(TD / 32, CD / 32, NB), dim3(32, 8)>>>(x, out);
    write_idx_kernel<<<NT / 256, 256>>>(out, out_size);
    finalize_kernel<<<1, 512>>>(out, out_size);
}